// round 12
// baseline (speedup 1.0000x reference)
#include <cuda_runtime.h>
#include <cuda_bf16.h>
#include <cstdint>

typedef __nv_bfloat16 bf16;
typedef unsigned short ushortT;

constexpr int BG=4, SEQ=1024, CH=1024, HEADS=16, HDIM=64;
constexpr int ROWS = BG * SEQ;
constexpr long long BG_STRIDE  = (long long)SEQ * CH;
constexpr long long PROB_BATCH = (long long)SEQ * SEQ;

// ---- persistent bf16 hi/lo scratch (allocation-free rule) ----
__device__ __align__(256) bf16 g_Xqh[ROWS*CH], g_Xql[ROWS*CH];
__device__ __align__(256) bf16 g_Xkh[ROWS*CH], g_Xkl[ROWS*CH];
__device__ __align__(256) bf16 g_Wqh[CH*CH],  g_Wql[CH*CH];
__device__ __align__(256) bf16 g_Wkh[CH*CH],  g_Wkl[CH*CH];
__device__ __align__(256) bf16 g_Wvh[CH*CH],  g_Wvl[CH*CH];
__device__ __align__(256) bf16 g_Woh[CH*CH],  g_Wol[CH*CH];
__device__ __align__(256) bf16 g_Qh[ROWS*CH], g_Ql[ROWS*CH];
__device__ __align__(256) bf16 g_Kh[ROWS*CH], g_Kl[ROWS*CH];
__device__ __align__(256) bf16 g_Vh[ROWS*CH], g_Vl[ROWS*CH];
__device__ __align__(256) bf16 g_Ch[ROWS*CH], g_Cl[ROWS*CH];
__device__ float g_rowsum[BG*HEADS*SEQ];

// ---------------------------------------------------------------------------
// helpers
// ---------------------------------------------------------------------------
__device__ __forceinline__ uint32_t pack2(ushortT lo, ushortT hi) {
    return (uint32_t)lo | ((uint32_t)hi << 16);
}
__device__ __forceinline__ void bsplit(float x, ushortT& h, ushortT& l) {
    __nv_bfloat16 hb = __float2bfloat16_rn(x);
    h = __bfloat16_as_ushort(hb);
    l = __bfloat16_as_ushort(__float2bfloat16_rn(x - __bfloat162float(hb)));
}
__device__ __forceinline__ void ldmx4(uint32_t& r0, uint32_t& r1, uint32_t& r2, uint32_t& r3, uint32_t a) {
    asm volatile("ldmatrix.sync.aligned.m8n8.x4.shared.b16 {%0,%1,%2,%3},[%4];"
                 : "=r"(r0), "=r"(r1), "=r"(r2), "=r"(r3) : "r"(a));
}
__device__ __forceinline__ void ldmx4t(uint32_t& r0, uint32_t& r1, uint32_t& r2, uint32_t& r3, uint32_t a) {
    asm volatile("ldmatrix.sync.aligned.m8n8.x4.trans.shared.b16 {%0,%1,%2,%3},[%4];"
                 : "=r"(r0), "=r"(r1), "=r"(r2), "=r"(r3) : "r"(a));
}
__device__ __forceinline__ void mma16816(float* c, uint32_t a0, uint32_t a1, uint32_t a2, uint32_t a3,
                                         uint32_t b0, uint32_t b1) {
    asm volatile(
        "mma.sync.aligned.m16n8k16.row.col.f32.bf16.bf16.f32 "
        "{%0,%1,%2,%3},{%4,%5,%6,%7},{%8,%9},{%0,%1,%2,%3};"
        : "+f"(c[0]), "+f"(c[1]), "+f"(c[2]), "+f"(c[3])
        : "r"(a0), "r"(a1), "r"(a2), "r"(a3), "r"(b0), "r"(b1));
}
__device__ __forceinline__ void cpa16(uint32_t dst, const void* src) {
    asm volatile("cp.async.cg.shared.global [%0],[%1],16;" :: "r"(dst), "l"(src));
}
#define CP_COMMIT() asm volatile("cp.async.commit_group;")
#define CP_WAIT1()  asm volatile("cp.async.wait_group 1;")
#define CP_WAIT0()  asm volatile("cp.async.wait_group 0;")

// ---------------------------------------------------------------------------
// Dense tile compute: 4 warps, warp tile 64x64. One 16-K subtile, 3 sweeps.
// Stage layout: [Ah | Al | Bh | Bl], each 128 x ASTR bf16.
// ---------------------------------------------------------------------------
constexpr int ASTR = 24;                  // 48B rows, conflict-free ldmatrix
constexpr int A_SZ = 128 * ASTR;          // 3072 elems per matrix
constexpr int D_STG = 4 * A_SZ;           // elems per stage
constexpr int SM_DENSE = 3 * D_STG * 2;   // 73728 B
constexpr int SM_SCORE = 4 * D_STG * 2;   // 98304 B (all of K=64 resident)

__device__ __forceinline__ void compute_tile(uint32_t sbase, int s, int wm, int wn,
                                             int lane, float acc[4][8][4])
{
    uint32_t s0 = sbase + (uint32_t)(s * D_STG) * 2;
    uint32_t ah[4][4], al[4][4];
    #pragma unroll
    for (int mt = 0; mt < 4; mt++) {
        int r = wm * 64 + mt * 16 + (lane & 15), c = (lane >> 4) << 3;
        ldmx4(ah[mt][0], ah[mt][1], ah[mt][2], ah[mt][3], s0 + (uint32_t)(r * ASTR + c) * 2);
        ldmx4(al[mt][0], al[mt][1], al[mt][2], al[mt][3], s0 + (uint32_t)(A_SZ + r * ASTR + c) * 2);
    }
    uint32_t b[8][2];
    #pragma unroll
    for (int p = 0; p < 4; p++) {
        int n = wn * 64 + p * 16 + (lane & 15), c = (lane >> 4) << 3;
        uint32_t r0, r1, r2, r3;
        ldmx4(r0, r1, r2, r3, s0 + (uint32_t)(2 * A_SZ + n * ASTR + c) * 2);
        b[2 * p][0] = r0; b[2 * p][1] = r2; b[2 * p + 1][0] = r1; b[2 * p + 1][1] = r3;
    }
    #pragma unroll
    for (int mt = 0; mt < 4; mt++)
        #pragma unroll
        for (int nt = 0; nt < 8; nt++)
            mma16816(acc[mt][nt], ah[mt][0], ah[mt][1], ah[mt][2], ah[mt][3], b[nt][0], b[nt][1]);
    #pragma unroll
    for (int mt = 0; mt < 4; mt++)
        #pragma unroll
        for (int nt = 0; nt < 8; nt++)
            mma16816(acc[mt][nt], al[mt][0], al[mt][1], al[mt][2], al[mt][3], b[nt][0], b[nt][1]);
    #pragma unroll
    for (int p = 0; p < 4; p++) {
        int n = wn * 64 + p * 16 + (lane & 15), c = (lane >> 4) << 3;
        uint32_t r0, r1, r2, r3;
        ldmx4(r0, r1, r2, r3, s0 + (uint32_t)(3 * A_SZ + n * ASTR + c) * 2);
        b[2 * p][0] = r0; b[2 * p][1] = r2; b[2 * p + 1][0] = r1; b[2 * p + 1][1] = r3;
    }
    #pragma unroll
    for (int mt = 0; mt < 4; mt++)
        #pragma unroll
        for (int nt = 0; nt < 8; nt++)
            mma16816(acc[mt][nt], ah[mt][0], ah[mt][1], ah[mt][2], ah[mt][3], b[nt][0], b[nt][1]);
}

// ---------------------------------------------------------------------------
// Dense bf16 NT GEMM body (K=1024): 128 threads, 3-stage ring, 1 barrier/iter.
// EPI: 0 = bias + fp32 out; 1 = bias + bf16 hi/lo out
// ---------------------------------------------------------------------------
template<int EPI>
__device__ __forceinline__ void gemm_body(
    const bf16* __restrict__ Ah, const bf16* __restrict__ Al,
    const bf16* __restrict__ Bh, const bf16* __restrict__ Bl,
    float* __restrict__ Cf, bf16* __restrict__ Coh, bf16* __restrict__ Col,
    const float* __restrict__ bias,
    int K, int lda, int ldb, int ldc, float scale, int row0, int col0)
{
    extern __shared__ bf16 sm[];
    const uint32_t sbase = (uint32_t)__cvta_generic_to_shared(sm);
    const int tid = threadIdx.x, lane = tid & 31, warp = tid >> 5;
    const int wm = warp >> 1, wn = warp & 1;

    auto loadS = [&](int kt, int s) {
        #pragma unroll
        for (int i = 0; i < 8; i++) {
            int e = tid + i * 128;
            int b = e >> 8, q = e & 255, row = q >> 1, ch = (q & 1) * 8;
            const bf16* base = (b == 0) ? Ah : (b == 1) ? Al : (b == 2) ? Bh : Bl;
            int rb = (b < 2) ? row0 : col0;
            int ld = (b < 2) ? lda : ldb;
            cpa16(sbase + (uint32_t)(s * D_STG + b * A_SZ + row * ASTR + ch) * 2,
                  base + (long long)(rb + row) * ld + kt * 16 + ch);
        }
        CP_COMMIT();
    };

    float acc[4][8][4];
    #pragma unroll
    for (int mt = 0; mt < 4; mt++)
        #pragma unroll
        for (int nt = 0; nt < 8; nt++)
            #pragma unroll
            for (int i = 0; i < 4; i++)
                acc[mt][nt][i] = 0.0f;

    const int NKI = K / 16;
    loadS(0, 0);
    if (NKI > 1) loadS(1, 1);
    for (int t = 0; t < NKI; t++) {
        if (t + 1 < NKI) CP_WAIT1(); else CP_WAIT0();
        __syncthreads();
        if (t + 2 < NKI) loadS(t + 2, (t + 2) % 3);
        compute_tile(sbase, t % 3, wm, wn, lane, acc);
    }

    #pragma unroll
    for (int mt = 0; mt < 4; mt++) {
        int r = row0 + wm * 64 + mt * 16 + (lane >> 2);
        #pragma unroll
        for (int nt = 0; nt < 8; nt++) {
            int c = col0 + wn * 64 + nt * 8 + ((lane & 3) << 1);
            float v0 = acc[mt][nt][0] * scale, v1 = acc[mt][nt][1] * scale;
            float v2 = acc[mt][nt][2] * scale, v3 = acc[mt][nt][3] * scale;
            float b0 = bias[c], b1 = bias[c + 1];
            if constexpr (EPI == 0) {
                *reinterpret_cast<float2*>(Cf + (long long)r * ldc + c)       = make_float2(v0 + b0, v1 + b1);
                *reinterpret_cast<float2*>(Cf + (long long)(r + 8) * ldc + c) = make_float2(v2 + b0, v3 + b1);
            } else {
                float x0 = v0 + b0, x1 = v1 + b1, x2 = v2 + b0, x3 = v3 + b1;
                ushortT h0, l0, h1, l1, h2, l2, h3, l3;
                bsplit(x0, h0, l0); bsplit(x1, h1, l1); bsplit(x2, h2, l2); bsplit(x3, h3, l3);
                *reinterpret_cast<uint32_t*>(Coh + (long long)r * ldc + c)       = pack2(h0, h1);
                *reinterpret_cast<uint32_t*>(Col + (long long)r * ldc + c)       = pack2(l0, l1);
                *reinterpret_cast<uint32_t*>(Coh + (long long)(r + 8) * ldc + c) = pack2(h2, h3);
                *reinterpret_cast<uint32_t*>(Col + (long long)(r + 8) * ldc + c) = pack2(l2, l3);
            }
        }
    }
}

// ---------------------------------------------------------------------------
// kernel wrappers (dense GEMMs)
// ---------------------------------------------------------------------------
struct ProjArgs {
    const bf16 *Ah[3], *Al[3], *Bh[3], *Bl[3];
    bf16 *Ch[3], *Cl[3];
    const float* bias[3];
};

__global__ __launch_bounds__(128, 2)
void proj_kernel(ProjArgs p)
{
    const int z = blockIdx.z;
    gemm_body<1>(p.Ah[z], p.Al[z], p.Bh[z], p.Bl[z],
                 nullptr, p.Ch[z], p.Cl[z], p.bias[z],
                 CH, CH, CH, CH, 1.0f, blockIdx.y * 128, blockIdx.x * 128);
}

__global__ __launch_bounds__(128, 2)
void out_kernel(const bf16* __restrict__ Ch, const bf16* __restrict__ Cl,
                const bf16* __restrict__ Wh, const bf16* __restrict__ Wl,
                float* __restrict__ out, const float* __restrict__ bo)
{
    gemm_body<0>(Ch, Cl, Wh, Wl, out, nullptr, nullptr, bo,
                 CH, CH, CH, CH, 1.0f, blockIdx.y * 128, blockIdx.x * 128);
}

// ---------------------------------------------------------------------------
// Scores kernel (K=64): whole K in smem, ONE barrier, 4 compute tiles,
// epilogue: E = exp(s/8) + rowsum atomics. 128 threads.
// ---------------------------------------------------------------------------
__global__ __launch_bounds__(128, 2)
void score_kernel(const bf16* __restrict__ Qh, const bf16* __restrict__ Ql,
                  const bf16* __restrict__ Kh, const bf16* __restrict__ Kl,
                  float* __restrict__ probs, float* __restrict__ rowsum)
{
    extern __shared__ bf16 sm[];
    const uint32_t sbase = (uint32_t)__cvta_generic_to_shared(sm);
    const int tid = threadIdx.x, lane = tid & 31, warp = tid >> 5;
    const int wm = warp >> 1, wn = warp & 1;
    const int z = blockIdx.z, zo = z >> 4, zi = z & 15;
    const long long off = zo * BG_STRIDE + (long long)zi * HDIM;
    const bf16* Ah = Qh + off; const bf16* Al = Ql + off;
    const bf16* Bh = Kh + off; const bf16* Bl = Kl + off;
    float* Cf = probs + (long long)z * PROB_BATCH;
    float* rs = rowsum + (long long)z * SEQ;
    const int row0 = blockIdx.y * 128, col0 = blockIdx.x * 128;

    // load ALL of K=64: 4 stages x 4 matrices x 256 chunks = 4096 cp.async
    #pragma unroll
    for (int i = 0; i < 32; i++) {
        int e = tid + i * 128;
        int b = e >> 10, q = e & 1023;
        int row = q >> 3, ch = q & 7;
        int st = ch >> 1, cc = ch & 1;
        const bf16* base = (b == 0) ? Ah : (b == 1) ? Al : (b == 2) ? Bh : Bl;
        int rb = (b < 2) ? row0 : col0;
        cpa16(sbase + (uint32_t)(st * D_STG + b * A_SZ + row * ASTR + cc * 8) * 2,
              base + (long long)(rb + row) * CH + ch * 8);
    }
    CP_COMMIT(); CP_WAIT0();
    __syncthreads();

    float acc[4][8][4];
    #pragma unroll
    for (int mt = 0; mt < 4; mt++)
        #pragma unroll
        for (int nt = 0; nt < 8; nt++)
            #pragma unroll
            for (int i = 0; i < 4; i++)
                acc[mt][nt][i] = 0.0f;

    #pragma unroll
    for (int st = 0; st < 4; st++)
        compute_tile(sbase, st, wm, wn, lane, acc);

    #pragma unroll
    for (int mt = 0; mt < 4; mt++) {
        int r = row0 + wm * 64 + mt * 16 + (lane >> 2);
        float rsA = 0.0f, rsB = 0.0f;
        #pragma unroll
        for (int nt = 0; nt < 8; nt++) {
            int c = col0 + wn * 64 + nt * 8 + ((lane & 3) << 1);
            float v0 = __expf(acc[mt][nt][0] * 0.125f), v1 = __expf(acc[mt][nt][1] * 0.125f);
            float v2 = __expf(acc[mt][nt][2] * 0.125f), v3 = __expf(acc[mt][nt][3] * 0.125f);
            rsA += v0 + v1; rsB += v2 + v3;
            *reinterpret_cast<float2*>(Cf + (long long)r * SEQ + c)       = make_float2(v0, v1);
            *reinterpret_cast<float2*>(Cf + (long long)(r + 8) * SEQ + c) = make_float2(v2, v3);
        }
        rsA += __shfl_xor_sync(0xFFFFFFFFu, rsA, 1);
        rsA += __shfl_xor_sync(0xFFFFFFFFu, rsA, 2);
        rsB += __shfl_xor_sync(0xFFFFFFFFu, rsB, 1);
        rsB += __shfl_xor_sync(0xFFFFFFFFu, rsB, 2);
        if ((lane & 3) == 0) {
            atomicAdd(&rs[r], rsA);
            atomicAdd(&rs[r + 8], rsB);
        }
    }
}

// ---------------------------------------------------------------------------
// Fused fp32 -> bf16 hi/lo splits (6 tensors) + rowsum zeroing, one launch.
// ---------------------------------------------------------------------------
struct SplitAll {
    const float* src[6];
    bf16 *h[6], *l[6];
    float* rsum;
};

__global__ __launch_bounds__(256)
void split_all(SplitAll a)
{
    int bx = blockIdx.x, t; long long blk;
    if (bx < 4096)      { t = 0; blk = bx; }
    else if (bx < 8192) { t = 1; blk = bx - 4096; }
    else { int r = bx - 8192; t = 2 + (r >> 10); blk = r & 1023; }

    long long i = (blk * 256 + threadIdx.x) * 4;
    float4 v = *reinterpret_cast<const float4*>(a.src[t] + i);
    ushortT hh[4], ll[4];
    bsplit(v.x, hh[0], ll[0]); bsplit(v.y, hh[1], ll[1]);
    bsplit(v.z, hh[2], ll[2]); bsplit(v.w, hh[3], ll[3]);
    *reinterpret_cast<uint2*>(a.h[t] + i) = make_uint2(pack2(hh[0], hh[1]), pack2(hh[2], hh[3]));
    *reinterpret_cast<uint2*>(a.l[t] + i) = make_uint2(pack2(ll[0], ll[1]), pack2(ll[2], ll[3]));

    if (bx < 64) {
        int j = bx * 1024 + threadIdx.x * 4;
        *reinterpret_cast<float4*>(a.rsum + j) = make_float4(0.f, 0.f, 0.f, 0.f);
    }
}

// ---------------------------------------------------------------------------
// PV kernel: 128 threads, 4 warps (warp tile 64x32). Reads E, normalizes by
// 1/rowsum, writes probs in place, computes context (bf16 hi/lo out).
// BM=128, BN=64, BK=32 fp32, K=SEQ. 1 barrier/iter; 2-stage P + 3-stage V.
// ---------------------------------------------------------------------------
constexpr int PSTR  = 40;                  // 80B rows, conflict-free 32-wide tiles
constexpr int VSTR  = 72;                  // 144B rows, conflict-free ldmatrix.trans 64-wide
constexpr int P_SZ  = 128 * PSTR;          // 5120
constexpr int V_SZ  = 32 * VSTR;           // 2304
constexpr int SM_PV = (4 * P_SZ + 6 * V_SZ) * 2;   // 68608 B

__global__ __launch_bounds__(128, 2)
void pv_kernel(float* __restrict__ P,
               const bf16* __restrict__ Vh, const bf16* __restrict__ Vl,
               const float* __restrict__ rowsum,
               bf16* __restrict__ Coh, bf16* __restrict__ Col)
{
    extern __shared__ bf16 sm[];
    const int tid = threadIdx.x, lane = tid & 31, warp = tid >> 5;
    const int wm = warp >> 1, wn = warp & 1;
    const int z = blockIdx.z, zo = z >> 4, zi = z & 15;
    const int row0 = blockIdx.y * 128;
    float* Pz = P + (long long)z * PROB_BATCH;
    const bf16* Vhz = Vh + zo * BG_STRIDE + (long long)zi * HDIM;
    const bf16* Vlz = Vl + zo * BG_STRIDE + (long long)zi * HDIM;
    const uint32_t sbase = (uint32_t)__cvta_generic_to_shared(sm);

    const float inv = 1.0f / rowsum[(long long)z * SEQ + row0 + tid];

    float4 e[8];
    auto loadE = [&](int m0) {
        const float* p = Pz + (long long)(row0 + tid) * SEQ + m0;
        #pragma unroll
        for (int j = 0; j < 8; j++)
            e[j] = *reinterpret_cast<const float4*>(p + 4 * j);
    };
    auto cpaV = [&](int m0, int st) {
        #pragma unroll
        for (int i = 0; i < 4; i++) {
            int q = tid + i * 128;
            int b = q >> 8, qq = q & 255;
            int vr = qq >> 3, vc = (qq & 7) * 8;
            const bf16* src = (b ? Vlz : Vhz) + (long long)(m0 + vr) * CH + vc;
            cpa16(sbase + (uint32_t)(4 * P_SZ + (st * 2 + b) * V_SZ + vr * VSTR + vc) * 2, src);
        }
        CP_COMMIT();
    };
    auto storeA = [&](int m0, int buf) {
        float w[32];
        #pragma unroll
        for (int j = 0; j < 8; j++) {
            w[4 * j + 0] = e[j].x * inv; w[4 * j + 1] = e[j].y * inv;
            w[4 * j + 2] = e[j].z * inv; w[4 * j + 3] = e[j].w * inv;
        }
        float* p = Pz + (long long)(row0 + tid) * SEQ + m0;
        #pragma unroll
        for (int j = 0; j < 8; j++)
            *reinterpret_cast<float4*>(p + 4 * j) = make_float4(w[4 * j], w[4 * j + 1], w[4 * j + 2], w[4 * j + 3]);
        ushortT hh[32], ll[32];
        #pragma unroll
        for (int j = 0; j < 32; j++) bsplit(w[j], hh[j], ll[j]);
        bf16* dh = sm + buf * 2 * P_SZ + tid * PSTR;
        #pragma unroll
        for (int qu = 0; qu < 4; qu++) {
            int o = qu * 8;
            *reinterpret_cast<uint4*>(dh + o) = make_uint4(
                pack2(hh[o + 0], hh[o + 1]), pack2(hh[o + 2], hh[o + 3]),
                pack2(hh[o + 4], hh[o + 5]), pack2(hh[o + 6], hh[o + 7]));
            *reinterpret_cast<uint4*>(dh + P_SZ + o) = make_uint4(
                pack2(ll[o + 0], ll[o + 1]), pack2(ll[o + 2], ll[o + 3]),
                pack2(ll[o + 4], ll[o + 5]), pack2(ll[o + 6], ll[o + 7]));
        }
    };

    float acc[4][4][4];
    #pragma unroll
    for (int mt = 0; mt < 4; mt++)
        #pragma unroll
        for (int nt = 0; nt < 4; nt++)
            #pragma unroll
            for (int i = 0; i < 4; i++)
                acc[mt][nt][i] = 0.0f;

    auto compute = [&](int t) {
        uint32_t pB = sbase + (uint32_t)((t & 1) * 2 * P_SZ) * 2;
        uint32_t vB = sbase + (uint32_t)(4 * P_SZ + (t % 3) * 2 * V_SZ) * 2;
        #pragma unroll
        for (int ks = 0; ks < 2; ks++) {
            uint32_t wh[4][4], wl[4][4];
            #pragma unroll
            for (int mt = 0; mt < 4; mt++) {
                int r = wm * 64 + mt * 16 + (lane & 15), c = ks * 16 + ((lane >> 4) << 3);
                ldmx4(wh[mt][0], wh[mt][1], wh[mt][2], wh[mt][3], pB + (uint32_t)(r * PSTR + c) * 2);
                ldmx4(wl[mt][0], wl[mt][1], wl[mt][2], wl[mt][3], pB + (uint32_t)(P_SZ + r * PSTR + c) * 2);
            }
            uint32_t bv[4][2];
            #pragma unroll
            for (int p = 0; p < 2; p++) {
                int kr = ks * 16 + (lane & 7) + ((lane >> 4) << 3);
                int nc = wn * 32 + p * 16 + (((lane >> 3) & 1) << 3);
                uint32_t r0, r1, r2, r3;
                ldmx4t(r0, r1, r2, r3, vB + (uint32_t)(kr * VSTR + nc) * 2);
                bv[2 * p][0] = r0; bv[2 * p][1] = r2; bv[2 * p + 1][0] = r1; bv[2 * p + 1][1] = r3;
            }
            #pragma unroll
            for (int mt = 0; mt < 4; mt++)
                #pragma unroll
                for (int nt = 0; nt < 4; nt++)
                    mma16816(acc[mt][nt], wh[mt][0], wh[mt][1], wh[mt][2], wh[mt][3], bv[nt][0], bv[nt][1]);
            #pragma unroll
            for (int mt = 0; mt < 4; mt++)
                #pragma unroll
                for (int nt = 0; nt < 4; nt++)
                    mma16816(acc[mt][nt], wl[mt][0], wl[mt][1], wl[mt][2], wl[mt][3], bv[nt][0], bv[nt][1]);
            #pragma unroll
            for (int p = 0; p < 2; p++) {
                int kr = ks * 16 + (lane & 7) + ((lane >> 4) << 3);
                int nc = wn * 32 + p * 16 + (((lane >> 3) & 1) << 3);
                uint32_t r0, r1, r2, r3;
                ldmx4t(r0, r1, r2, r3, vB + (uint32_t)(V_SZ + kr * VSTR + nc) * 2);
                bv[2 * p][0] = r0; bv[2 * p][1] = r2; bv[2 * p + 1][0] = r1; bv[2 * p + 1][1] = r3;
            }
            #pragma unroll
            for (int mt = 0; mt < 4; mt++)
                #pragma unroll
                for (int nt = 0; nt < 4; nt++)
                    mma16816(acc[mt][nt], wh[mt][0], wh[mt][1], wh[mt][2], wh[mt][3], bv[nt][0], bv[nt][1]);
        }
    };

    constexpr int NKI = SEQ / 32;
    loadE(0);
    storeA(0, 0);
    cpaV(0, 0);
    for (int t = 0; t < NKI; t++) {
        if (t + 1 < NKI) { loadE((t + 1) * 32); cpaV((t + 1) * 32, (t + 1) % 3); CP_WAIT1(); }
        else             { CP_WAIT0(); }
        __syncthreads();                  // V(t) visible; all done compute(t-1)
        if (t + 1 < NKI) storeA((t + 1) * 32, (t + 1) & 1);
        compute(t);
    }

    // epilogue: split context to bf16 hi/lo
    bf16* Chz = Coh + zo * BG_STRIDE + (long long)zi * HDIM;
    bf16* Clz = Col + zo * BG_STRIDE + (long long)zi * HDIM;
    #pragma unroll
    for (int mt = 0; mt < 4; mt++) {
        int r = row0 + wm * 64 + mt * 16 + (lane >> 2);
        #pragma unroll
        for (int nt = 0; nt < 4; nt++) {
            int c = wn * 32 + nt * 8 + ((lane & 3) << 1);
            ushortT h0, l0, h1, l1, h2, l2, h3, l3;
            bsplit(acc[mt][nt][0], h0, l0); bsplit(acc[mt][nt][1], h1, l1);
            bsplit(acc[mt][nt][2], h2, l2); bsplit(acc[mt][nt][3], h3, l3);
            *reinterpret_cast<uint32_t*>(Chz + (long long)r * CH + c)       = pack2(h0, h1);
            *reinterpret_cast<uint32_t*>(Clz + (long long)r * CH + c)       = pack2(l0, l1);
            *reinterpret_cast<uint32_t*>(Chz + (long long)(r + 8) * CH + c) = pack2(h2, h3);
            *reinterpret_cast<uint32_t*>(Clz + (long long)(r + 8) * CH + c) = pack2(l2, l3);
        }
    }
}

// ---------------------------------------------------------------------------
// Launch
// ---------------------------------------------------------------------------
extern "C" void kernel_launch(void* const* d_in, const int* in_sizes, int n_in,
                              void* d_out, int out_size)
{
    const float* xq  = (const float*)d_in[0];
    const float* xkv = (const float*)d_in[1];
    const float* Wq  = (const float*)d_in[2];
    const float* bq  = (const float*)d_in[3];
    const float* Wk  = (const float*)d_in[4];
    const float* bk  = (const float*)d_in[5];
    const float* Wv  = (const float*)d_in[6];
    const float* bv  = (const float*)d_in[7];
    const float* Wo  = (const float*)d_in[8];
    const float* bo  = (const float*)d_in[9];

    float* out   = (float*)d_out;
    float* probs = out + (long long)ROWS * CH;

    bf16 *Xqh, *Xql, *Xkh, *Xkl, *Wqh, *Wql, *Wkh, *Wkl, *Wvh, *Wvl, *Woh, *Wol;
    bf16 *Qh, *Ql, *Kh, *Kl, *Vh, *Vl, *Ch, *Cl;
    float* rsum;
    cudaGetSymbolAddress((void**)&Xqh, g_Xqh); cudaGetSymbolAddress((void**)&Xql, g_Xql);
    cudaGetSymbolAddress((void**)&Xkh, g_Xkh); cudaGetSymbolAddress((void**)&Xkl, g_Xkl);
    cudaGetSymbolAddress((void**)&Wqh, g_Wqh); cudaGetSymbolAddress((void**)&Wql, g_Wql);
    cudaGetSymbolAddress((void**)&Wkh, g_Wkh); cudaGetSymbolAddress((void**)&Wkl, g_Wkl);
    cudaGetSymbolAddress((void**)&Wvh, g_Wvh); cudaGetSymbolAddress((void**)&Wvl, g_Wvl);
    cudaGetSymbolAddress((void**)&Woh, g_Woh); cudaGetSymbolAddress((void**)&Wol, g_Wol);
    cudaGetSymbolAddress((void**)&Qh, g_Qh);   cudaGetSymbolAddress((void**)&Ql, g_Ql);
    cudaGetSymbolAddress((void**)&Kh, g_Kh);   cudaGetSymbolAddress((void**)&Kl, g_Kl);
    cudaGetSymbolAddress((void**)&Vh, g_Vh);   cudaGetSymbolAddress((void**)&Vl, g_Vl);
    cudaGetSymbolAddress((void**)&Ch, g_Ch);   cudaGetSymbolAddress((void**)&Cl, g_Cl);
    cudaGetSymbolAddress((void**)&rsum, g_rowsum);

    cudaFuncSetAttribute((const void*)proj_kernel,  cudaFuncAttributeMaxDynamicSharedMemorySize, SM_DENSE);
    cudaFuncSetAttribute((const void*)out_kernel,   cudaFuncAttributeMaxDynamicSharedMemorySize, SM_DENSE);
    cudaFuncSetAttribute((const void*)score_kernel, cudaFuncAttributeMaxDynamicSharedMemorySize, SM_SCORE);
    cudaFuncSetAttribute((const void*)pv_kernel,    cudaFuncAttributeMaxDynamicSharedMemorySize, SM_PV);

    // 0. fused splits (xq, xkv, Wq, Wk, Wv, Wo) + rowsum zeroing, one launch
    SplitAll sa;
    sa.src[0] = xq;  sa.h[0] = Xqh; sa.l[0] = Xql;
    sa.src[1] = xkv; sa.h[1] = Xkh; sa.l[1] = Xkl;
    sa.src[2] = Wq;  sa.h[2] = Wqh; sa.l[2] = Wql;
    sa.src[3] = Wk;  sa.h[3] = Wkh; sa.l[3] = Wkl;
    sa.src[4] = Wv;  sa.h[4] = Wvh; sa.l[4] = Wvl;
    sa.src[5] = Wo;  sa.h[5] = Woh; sa.l[5] = Wol;
    sa.rsum = rsum;
    split_all<<<2 * 4096 + 4 * 1024, 256>>>(sa);

    // 1. fused Q/K/V projections (grid.z = 3)
    ProjArgs pa;
    pa.Ah[0] = Xqh; pa.Al[0] = Xql; pa.Bh[0] = Wqh; pa.Bl[0] = Wql; pa.Ch[0] = Qh; pa.Cl[0] = Ql; pa.bias[0] = bq;
    pa.Ah[1] = Xkh; pa.Al[1] = Xkl; pa.Bh[1] = Wkh; pa.Bl[1] = Wkl; pa.Ch[1] = Kh; pa.Cl[1] = Kl; pa.bias[1] = bk;
    pa.Ah[2] = Xkh; pa.Al[2] = Xkl; pa.Bh[2] = Wvh; pa.Bl[2] = Wvl; pa.Ch[2] = Vh; pa.Cl[2] = Vl; pa.bias[2] = bv;
    proj_kernel<<<dim3(CH / 128, ROWS / 128, 3), 128, SM_DENSE>>>(pa);

    // 2. scores: E = exp(s/8) + row sums (single-phase, K resident)
    score_kernel<<<dim3(SEQ / 128, SEQ / 128, BG * HEADS), 128, SM_SCORE>>>(Qh, Ql, Kh, Kl, probs, rsum);

    // 3. PV: normalize probs in place + context (bf16 hi/lo)
    pv_kernel<<<dim3(1, SEQ / 128, BG * HEADS), 128, SM_PV>>>(probs, Vh, Vl, rsum, Ch, Cl);

    // 4. output projection (fp32 out)
    out_kernel<<<dim3(CH / 128, ROWS / 128, 1), 128, SM_DENSE>>>(Ch, Cl, Woh, Wol, out, bo);
}

// round 14
// speedup vs baseline: 1.1133x; 1.1133x over previous
#include <cuda_runtime.h>
#include <cuda_bf16.h>
#include <cstdint>

typedef __nv_bfloat16 bf16;
typedef unsigned short ushortT;

constexpr int BG=4, SEQ=1024, CH=1024, HEADS=16, HDIM=64;
constexpr int ROWS = BG * SEQ;
constexpr long long BG_STRIDE  = (long long)SEQ * CH;
constexpr long long PROB_BATCH = (long long)SEQ * SEQ;

// ---- persistent bf16 hi/lo scratch (allocation-free rule) ----
__device__ __align__(256) bf16 g_Xqh[ROWS*CH], g_Xql[ROWS*CH];
__device__ __align__(256) bf16 g_Xkh[ROWS*CH], g_Xkl[ROWS*CH];
__device__ __align__(256) bf16 g_Wqh[CH*CH],  g_Wql[CH*CH];
__device__ __align__(256) bf16 g_Wkh[CH*CH],  g_Wkl[CH*CH];
__device__ __align__(256) bf16 g_Wvh[CH*CH],  g_Wvl[CH*CH];
__device__ __align__(256) bf16 g_Woh[CH*CH],  g_Wol[CH*CH];
__device__ __align__(256) bf16 g_Qh[ROWS*CH], g_Ql[ROWS*CH];
__device__ __align__(256) bf16 g_Kh[ROWS*CH], g_Kl[ROWS*CH];
__device__ __align__(256) bf16 g_Vh[ROWS*CH], g_Vl[ROWS*CH];
__device__ __align__(256) bf16 g_Ch[ROWS*CH], g_Cl[ROWS*CH];
__device__ float g_rowsum[BG*HEADS*SEQ];

// ---------------------------------------------------------------------------
// helpers
// ---------------------------------------------------------------------------
__device__ __forceinline__ uint32_t pack2(ushortT lo, ushortT hi) {
    return (uint32_t)lo | ((uint32_t)hi << 16);
}
__device__ __forceinline__ void bsplit(float x, ushortT& h, ushortT& l) {
    __nv_bfloat16 hb = __float2bfloat16_rn(x);
    h = __bfloat16_as_ushort(hb);
    l = __bfloat16_as_ushort(__float2bfloat16_rn(x - __bfloat162float(hb)));
}
__device__ __forceinline__ void ldmx4(uint32_t& r0, uint32_t& r1, uint32_t& r2, uint32_t& r3, uint32_t a) {
    asm volatile("ldmatrix.sync.aligned.m8n8.x4.shared.b16 {%0,%1,%2,%3},[%4];"
                 : "=r"(r0), "=r"(r1), "=r"(r2), "=r"(r3) : "r"(a));
}
__device__ __forceinline__ void ldmx4t(uint32_t& r0, uint32_t& r1, uint32_t& r2, uint32_t& r3, uint32_t a) {
    asm volatile("ldmatrix.sync.aligned.m8n8.x4.trans.shared.b16 {%0,%1,%2,%3},[%4];"
                 : "=r"(r0), "=r"(r1), "=r"(r2), "=r"(r3) : "r"(a));
}
__device__ __forceinline__ void mma16816(float* c, uint32_t a0, uint32_t a1, uint32_t a2, uint32_t a3,
                                         uint32_t b0, uint32_t b1) {
    asm volatile(
        "mma.sync.aligned.m16n8k16.row.col.f32.bf16.bf16.f32 "
        "{%0,%1,%2,%3},{%4,%5,%6,%7},{%8,%9},{%0,%1,%2,%3};"
        : "+f"(c[0]), "+f"(c[1]), "+f"(c[2]), "+f"(c[3])
        : "r"(a0), "r"(a1), "r"(a2), "r"(a3), "r"(b0), "r"(b1));
}
__device__ __forceinline__ void cpa16(uint32_t dst, const void* src) {
    asm volatile("cp.async.cg.shared.global [%0],[%1],16;" :: "r"(dst), "l"(src));
}
#define CP_COMMIT() asm volatile("cp.async.commit_group;")
#define CP_WAIT1()  asm volatile("cp.async.wait_group 1;")
#define CP_WAIT0()  asm volatile("cp.async.wait_group 0;")

// ---------------------------------------------------------------------------
// Shared dense-tile compute: one 16-K-subtile, 3 sweeps (AhBh, AlBh, AhBl).
// 8 warps (4x2), warp tile 32x64. Stage layout: [Ah | Al | Bh | Bl].
// ---------------------------------------------------------------------------
constexpr int ASTR = 24;                  // 48B rows, conflict-free ldmatrix
constexpr int A_SZ = 128 * ASTR;          // 3072 elems per matrix
constexpr int D_STG = 4 * A_SZ;           // elems per stage
constexpr int SM_DENSE = 3 * D_STG * 2;   // 73728 B
constexpr int SM_SCORE = 4 * D_STG * 2;   // 98304 B (all of K=64 resident)

__device__ __forceinline__ void compute_tile(uint32_t sbase, int s, int wm, int wn,
                                             int lane, float acc[2][8][4])
{
    uint32_t s0 = sbase + (uint32_t)(s * D_STG) * 2;
    uint32_t ah[2][4], al[2][4];
    #pragma unroll
    for (int mt = 0; mt < 2; mt++) {
        int r = wm * 32 + mt * 16 + (lane & 15), c = (lane >> 4) << 3;
        ldmx4(ah[mt][0], ah[mt][1], ah[mt][2], ah[mt][3], s0 + (uint32_t)(r * ASTR + c) * 2);
        ldmx4(al[mt][0], al[mt][1], al[mt][2], al[mt][3], s0 + (uint32_t)(A_SZ + r * ASTR + c) * 2);
    }
    uint32_t b[8][2];
    #pragma unroll
    for (int p = 0; p < 4; p++) {
        int n = wn * 64 + p * 16 + (lane & 15), c = (lane >> 4) << 3;
        uint32_t r0, r1, r2, r3;
        ldmx4(r0, r1, r2, r3, s0 + (uint32_t)(2 * A_SZ + n * ASTR + c) * 2);
        b[2 * p][0] = r0; b[2 * p][1] = r2; b[2 * p + 1][0] = r1; b[2 * p + 1][1] = r3;
    }
    #pragma unroll
    for (int mt = 0; mt < 2; mt++)
        #pragma unroll
        for (int nt = 0; nt < 8; nt++)
            mma16816(acc[mt][nt], ah[mt][0], ah[mt][1], ah[mt][2], ah[mt][3], b[nt][0], b[nt][1]);
    #pragma unroll
    for (int mt = 0; mt < 2; mt++)
        #pragma unroll
        for (int nt = 0; nt < 8; nt++)
            mma16816(acc[mt][nt], al[mt][0], al[mt][1], al[mt][2], al[mt][3], b[nt][0], b[nt][1]);
    #pragma unroll
    for (int p = 0; p < 4; p++) {
        int n = wn * 64 + p * 16 + (lane & 15), c = (lane >> 4) << 3;
        uint32_t r0, r1, r2, r3;
        ldmx4(r0, r1, r2, r3, s0 + (uint32_t)(3 * A_SZ + n * ASTR + c) * 2);
        b[2 * p][0] = r0; b[2 * p][1] = r2; b[2 * p + 1][0] = r1; b[2 * p + 1][1] = r3;
    }
    #pragma unroll
    for (int mt = 0; mt < 2; mt++)
        #pragma unroll
        for (int nt = 0; nt < 8; nt++)
            mma16816(acc[mt][nt], ah[mt][0], ah[mt][1], ah[mt][2], ah[mt][3], b[nt][0], b[nt][1]);
}

// ---------------------------------------------------------------------------
// Dense bf16 NT GEMM body (K=1024): 3-stage ring, ONE barrier per k-tile.
// EPI: 0 = bias + fp32 out; 1 = bias + bf16 hi/lo out
// ---------------------------------------------------------------------------
template<int EPI>
__device__ __forceinline__ void gemm_body(
    const bf16* __restrict__ Ah, const bf16* __restrict__ Al,
    const bf16* __restrict__ Bh, const bf16* __restrict__ Bl,
    float* __restrict__ Cf, bf16* __restrict__ Coh, bf16* __restrict__ Col,
    const float* __restrict__ bias,
    int K, int lda, int ldb, int ldc, float scale, int row0, int col0)
{
    extern __shared__ bf16 sm[];
    const uint32_t sbase = (uint32_t)__cvta_generic_to_shared(sm);
    const int tid = threadIdx.x, lane = tid & 31, warp = tid >> 5;
    const int wm = warp >> 1, wn = warp & 1;

    auto loadS = [&](int kt, int s) {
        #pragma unroll
        for (int i = 0; i < 4; i++) {
            int e = tid + i * 256;
            int b = e >> 8, q = e & 255, row = q >> 1, ch = (q & 1) * 8;
            const bf16* base = (b == 0) ? Ah : (b == 1) ? Al : (b == 2) ? Bh : Bl;
            int rb = (b < 2) ? row0 : col0;
            int ld = (b < 2) ? lda : ldb;
            cpa16(sbase + (uint32_t)(s * D_STG + b * A_SZ + row * ASTR + ch) * 2,
                  base + (long long)(rb + row) * ld + kt * 16 + ch);
        }
        CP_COMMIT();
    };

    float acc[2][8][4];
    #pragma unroll
    for (int mt = 0; mt < 2; mt++)
        #pragma unroll
        for (int nt = 0; nt < 8; nt++)
            #pragma unroll
            for (int i = 0; i < 4; i++)
                acc[mt][nt][i] = 0.0f;

    const int NKI = K / 16;
    loadS(0, 0);
    if (NKI > 1) loadS(1, 1);
    for (int t = 0; t < NKI; t++) {
        if (t + 1 < NKI) CP_WAIT1(); else CP_WAIT0();
        __syncthreads();
        if (t + 2 < NKI) loadS(t + 2, (t + 2) % 3);
        compute_tile(sbase, t % 3, wm, wn, lane, acc);
    }

    #pragma unroll
    for (int mt = 0; mt < 2; mt++) {
        int r = row0 + wm * 32 + mt * 16 + (lane >> 2);
        #pragma unroll
        for (int nt = 0; nt < 8; nt++) {
            int c = col0 + wn * 64 + nt * 8 + ((lane & 3) << 1);
            float v0 = acc[mt][nt][0] * scale, v1 = acc[mt][nt][1] * scale;
            float v2 = acc[mt][nt][2] * scale, v3 = acc[mt][nt][3] * scale;
            float b0 = bias[c], b1 = bias[c + 1];
            if constexpr (EPI == 0) {
                *reinterpret_cast<float2*>(Cf + (long long)r * ldc + c)       = make_float2(v0 + b0, v1 + b1);
                *reinterpret_cast<float2*>(Cf + (long long)(r + 8) * ldc + c) = make_float2(v2 + b0, v3 + b1);
            } else {
                float x0 = v0 + b0, x1 = v1 + b1, x2 = v2 + b0, x3 = v3 + b1;
                ushortT h0, l0, h1, l1, h2, l2, h3, l3;
                bsplit(x0, h0, l0); bsplit(x1, h1, l1); bsplit(x2, h2, l2); bsplit(x3, h3, l3);
                *reinterpret_cast<uint32_t*>(Coh + (long long)r * ldc + c)       = pack2(h0, h1);
                *reinterpret_cast<uint32_t*>(Col + (long long)r * ldc + c)       = pack2(l0, l1);
                *reinterpret_cast<uint32_t*>(Coh + (long long)(r + 8) * ldc + c) = pack2(h2, h3);
                *reinterpret_cast<uint32_t*>(Col + (long long)(r + 8) * ldc + c) = pack2(l2, l3);
            }
        }
    }
}

// ---------------------------------------------------------------------------
// kernel wrappers (dense GEMMs)
// ---------------------------------------------------------------------------
struct ProjArgs {
    const bf16 *Ah[3], *Al[3], *Bh[3], *Bl[3];
    bf16 *Ch[3], *Cl[3];
    const float* bias[3];
};

__global__ __launch_bounds__(256, 2)
void proj_kernel(ProjArgs p)
{
    const int z = blockIdx.z;
    gemm_body<1>(p.Ah[z], p.Al[z], p.Bh[z], p.Bl[z],
                 nullptr, p.Ch[z], p.Cl[z], p.bias[z],
                 CH, CH, CH, CH, 1.0f, blockIdx.y * 128, blockIdx.x * 128);
}

__global__ __launch_bounds__(256, 2)
void out_kernel(const bf16* __restrict__ Ch, const bf16* __restrict__ Cl,
                const bf16* __restrict__ Wh, const bf16* __restrict__ Wl,
                float* __restrict__ out, const float* __restrict__ bo)
{
    gemm_body<0>(Ch, Cl, Wh, Wl, out, nullptr, nullptr, bo,
                 CH, CH, CH, CH, 1.0f, blockIdx.y * 128, blockIdx.x * 128);
}

// ---------------------------------------------------------------------------
// Scores kernel (K=64): whole K in smem, ONE barrier, 4 compute tiles,
// epilogue: E = exp(s/8) + rowsum atomics.
// ---------------------------------------------------------------------------
__global__ __launch_bounds__(256, 2)
void score_kernel(const bf16* __restrict__ Qh, const bf16* __restrict__ Ql,
                  const bf16* __restrict__ Kh, const bf16* __restrict__ Kl,
                  float* __restrict__ probs, float* __restrict__ rowsum)
{
    extern __shared__ bf16 sm[];
    const uint32_t sbase = (uint32_t)__cvta_generic_to_shared(sm);
    const int tid = threadIdx.x, lane = tid & 31, warp = tid >> 5;
    const int wm = warp >> 1, wn = warp & 1;
    const int z = blockIdx.z, zo = z >> 4, zi = z & 15;
    const long long off = zo * BG_STRIDE + (long long)zi * HDIM;
    const bf16* Ah = Qh + off; const bf16* Al = Ql + off;
    const bf16* Bh = Kh + off; const bf16* Bl = Kl + off;
    float* Cf = probs + (long long)z * PROB_BATCH;
    float* rs = rowsum + (long long)z * SEQ;
    const int row0 = blockIdx.y * 128, col0 = blockIdx.x * 128;

    // load ALL of K=64: 4 stages x 4 matrices x 256 chunks = 4096 cp.async
    #pragma unroll
    for (int i = 0; i < 16; i++) {
        int e = tid + i * 256;
        int b = e >> 10, q = e & 1023;
        int row = q >> 3, ch = q & 7;
        int st = ch >> 1, cc = ch & 1;
        const bf16* base = (b == 0) ? Ah : (b == 1) ? Al : (b == 2) ? Bh : Bl;
        int rb = (b < 2) ? row0 : col0;
        cpa16(sbase + (uint32_t)(st * D_STG + b * A_SZ + row * ASTR + cc * 8) * 2,
              base + (long long)(rb + row) * CH + ch * 8);
    }
    CP_COMMIT(); CP_WAIT0();
    __syncthreads();

    float acc[2][8][4];
    #pragma unroll
    for (int mt = 0; mt < 2; mt++)
        #pragma unroll
        for (int nt = 0; nt < 8; nt++)
            #pragma unroll
            for (int i = 0; i < 4; i++)
                acc[mt][nt][i] = 0.0f;

    #pragma unroll
    for (int st = 0; st < 4; st++)
        compute_tile(sbase, st, wm, wn, lane, acc);

    #pragma unroll
    for (int mt = 0; mt < 2; mt++) {
        int r = row0 + wm * 32 + mt * 16 + (lane >> 2);
        float rsA = 0.0f, rsB = 0.0f;
        #pragma unroll
        for (int nt = 0; nt < 8; nt++) {
            int c = col0 + wn * 64 + nt * 8 + ((lane & 3) << 1);
            float v0 = __expf(acc[mt][nt][0] * 0.125f), v1 = __expf(acc[mt][nt][1] * 0.125f);
            float v2 = __expf(acc[mt][nt][2] * 0.125f), v3 = __expf(acc[mt][nt][3] * 0.125f);
            rsA += v0 + v1; rsB += v2 + v3;
            *reinterpret_cast<float2*>(Cf + (long long)r * SEQ + c)       = make_float2(v0, v1);
            *reinterpret_cast<float2*>(Cf + (long long)(r + 8) * SEQ + c) = make_float2(v2, v3);
        }
        rsA += __shfl_xor_sync(0xFFFFFFFFu, rsA, 1);
        rsA += __shfl_xor_sync(0xFFFFFFFFu, rsA, 2);
        rsB += __shfl_xor_sync(0xFFFFFFFFu, rsB, 1);
        rsB += __shfl_xor_sync(0xFFFFFFFFu, rsB, 2);
        if ((lane & 3) == 0) {
            atomicAdd(&rs[r], rsA);
            atomicAdd(&rs[r + 8], rsB);
        }
    }
}

// ---------------------------------------------------------------------------
// Fused fp32 -> bf16 hi/lo splits (6 tensors) + rowsum zeroing, one launch.
// ---------------------------------------------------------------------------
struct SplitAll {
    const float* src[6];
    bf16 *h[6], *l[6];
    float* rsum;
};

__global__ __launch_bounds__(256)
void split_all(SplitAll a)
{
    int bx = blockIdx.x, t; long long blk;
    if (bx < 4096)      { t = 0; blk = bx; }
    else if (bx < 8192) { t = 1; blk = bx - 4096; }
    else { int r = bx - 8192; t = 2 + (r >> 10); blk = r & 1023; }

    long long i = (blk * 256 + threadIdx.x) * 4;
    float4 v = *reinterpret_cast<const float4*>(a.src[t] + i);
    ushortT hh[4], ll[4];
    bsplit(v.x, hh[0], ll[0]); bsplit(v.y, hh[1], ll[1]);
    bsplit(v.z, hh[2], ll[2]); bsplit(v.w, hh[3], ll[3]);
    *reinterpret_cast<uint2*>(a.h[t] + i) = make_uint2(pack2(hh[0], hh[1]), pack2(hh[2], hh[3]));
    *reinterpret_cast<uint2*>(a.l[t] + i) = make_uint2(pack2(ll[0], ll[1]), pack2(ll[2], ll[3]));

    if (bx < 64) {
        int j = bx * 1024 + threadIdx.x * 4;
        *reinterpret_cast<float4*>(a.rsum + j) = make_float4(0.f, 0.f, 0.f, 0.f);
    }
}

// ---------------------------------------------------------------------------
// PV kernel: 256 threads, 8 warps (warp tile 32x32). Reads E, normalizes by
// 1/rowsum, writes probs in place, computes context (bf16 hi/lo out).
// BM=128, BN=64, BK=32 fp32, K=SEQ. 1 barrier/iter; 2-stage P + 3-stage V.
// KEY CHANGE vs R11: storeA(t+1) moved AFTER compute(t) so the E-loads and
// probs STGs issued at the top of the iteration are covered by the mma phase.
// ---------------------------------------------------------------------------
constexpr int PSTR  = 40;                  // 80B rows, conflict-free 32-wide tiles
constexpr int VSTR  = 72;                  // 144B rows, conflict-free ldmatrix.trans 64-wide
constexpr int P_SZ  = 128 * PSTR;          // 5120
constexpr int V_SZ  = 32 * VSTR;           // 2304
constexpr int SM_PV = (4 * P_SZ + 6 * V_SZ) * 2;   // 68608 B

__global__ __launch_bounds__(256, 2)
void pv_kernel(float* __restrict__ P,
               const bf16* __restrict__ Vh, const bf16* __restrict__ Vl,
               const float* __restrict__ rowsum,
               bf16* __restrict__ Coh, bf16* __restrict__ Col)
{
    extern __shared__ bf16 sm[];
    const int tid = threadIdx.x, lane = tid & 31, warp = tid >> 5;
    const int wm = warp >> 1, wn = warp & 1;
    const int z = blockIdx.z, zo = z >> 4, zi = z & 15;
    const int row0 = blockIdx.y * 128;
    float* Pz = P + (long long)z * PROB_BATCH;
    const bf16* Vhz = Vh + zo * BG_STRIDE + (long long)zi * HDIM;
    const bf16* Vlz = Vl + zo * BG_STRIDE + (long long)zi * HDIM;
    const uint32_t sbase = (uint32_t)__cvta_generic_to_shared(sm);

    const int ar = tid >> 1, ac = (tid & 1) * 16;
    const float inv = 1.0f / rowsum[(long long)z * SEQ + row0 + ar];

    float4 e[4];
    auto loadE = [&](int m0) {
        const float* p = Pz + (long long)(row0 + ar) * SEQ + m0 + ac;
        e[0] = *reinterpret_cast<const float4*>(p);
        e[1] = *reinterpret_cast<const float4*>(p + 4);
        e[2] = *reinterpret_cast<const float4*>(p + 8);
        e[3] = *reinterpret_cast<const float4*>(p + 12);
    };
    auto cpaV = [&](int m0, int st) {
        #pragma unroll
        for (int i = 0; i < 2; i++) {
            int q = (tid + i * 256);
            int b = q >> 8, qq = q & 255;
            int vr = qq >> 3, vc = (qq & 7) * 8;
            const bf16* src = (b ? Vlz : Vhz) + (long long)(m0 + vr) * CH + vc;
            cpa16(sbase + (uint32_t)(4 * P_SZ + (st * 2 + b) * V_SZ + vr * VSTR + vc) * 2, src);
        }
        CP_COMMIT();
    };
    auto storeA = [&](int m0, int buf) {
        float w[16];
        #pragma unroll
        for (int j = 0; j < 4; j++) {
            w[4 * j + 0] = e[j].x * inv; w[4 * j + 1] = e[j].y * inv;
            w[4 * j + 2] = e[j].z * inv; w[4 * j + 3] = e[j].w * inv;
        }
        float* p = Pz + (long long)(row0 + ar) * SEQ + m0 + ac;
        #pragma unroll
        for (int j = 0; j < 4; j++)
            *reinterpret_cast<float4*>(p + 4 * j) = make_float4(w[4 * j], w[4 * j + 1], w[4 * j + 2], w[4 * j + 3]);
        ushortT hh[16], ll[16];
        #pragma unroll
        for (int j = 0; j < 16; j++) bsplit(w[j], hh[j], ll[j]);
        bf16* dh = sm + buf * 2 * P_SZ + ar * PSTR + ac;
        #pragma unroll
        for (int half = 0; half < 2; half++) {
            int o = half * 8;
            *reinterpret_cast<uint4*>(dh + o) = make_uint4(
                pack2(hh[o + 0], hh[o + 1]), pack2(hh[o + 2], hh[o + 3]),
                pack2(hh[o + 4], hh[o + 5]), pack2(hh[o + 6], hh[o + 7]));
            *reinterpret_cast<uint4*>(dh + P_SZ + o) = make_uint4(
                pack2(ll[o + 0], ll[o + 1]), pack2(ll[o + 2], ll[o + 3]),
                pack2(ll[o + 4], ll[o + 5]), pack2(ll[o + 6], ll[o + 7]));
        }
    };

    float acc[2][4][4];
    #pragma unroll
    for (int mt = 0; mt < 2; mt++)
        #pragma unroll
        for (int nt = 0; nt < 4; nt++)
            #pragma unroll
            for (int i = 0; i < 4; i++)
                acc[mt][nt][i] = 0.0f;

    auto compute = [&](int t) {
        uint32_t pB = sbase + (uint32_t)((t & 1) * 2 * P_SZ) * 2;
        uint32_t vB = sbase + (uint32_t)(4 * P_SZ + (t % 3) * 2 * V_SZ) * 2;
        #pragma unroll
        for (int ks = 0; ks < 2; ks++) {
            uint32_t wh[2][4], wl[2][4];
            #pragma unroll
            for (int mt = 0; mt < 2; mt++) {
                int r = wm * 32 + mt * 16 + (lane & 15), c = ks * 16 + ((lane >> 4) << 3);
                ldmx4(wh[mt][0], wh[mt][1], wh[mt][2], wh[mt][3], pB + (uint32_t)(r * PSTR + c) * 2);
                ldmx4(wl[mt][0], wl[mt][1], wl[mt][2], wl[mt][3], pB + (uint32_t)(P_SZ + r * PSTR + c) * 2);
            }
            uint32_t bv[4][2];
            #pragma unroll
            for (int p = 0; p < 2; p++) {
                int kr = ks * 16 + (lane & 7) + ((lane >> 4) << 3);
                int nc = wn * 32 + p * 16 + (((lane >> 3) & 1) << 3);
                uint32_t r0, r1, r2, r3;
                ldmx4t(r0, r1, r2, r3, vB + (uint32_t)(kr * VSTR + nc) * 2);
                bv[2 * p][0] = r0; bv[2 * p][1] = r2; bv[2 * p + 1][0] = r1; bv[2 * p + 1][1] = r3;
            }
            #pragma unroll
            for (int mt = 0; mt < 2; mt++)
                #pragma unroll
                for (int nt = 0; nt < 4; nt++)
                    mma16816(acc[mt][nt], wh[mt][0], wh[mt][1], wh[mt][2], wh[mt][3], bv[nt][0], bv[nt][1]);
            #pragma unroll
            for (int mt = 0; mt < 2; mt++)
                #pragma unroll
                for (int nt = 0; nt < 4; nt++)
                    mma16816(acc[mt][nt], wl[mt][0], wl[mt][1], wl[mt][2], wl[mt][3], bv[nt][0], bv[nt][1]);
            #pragma unroll
            for (int p = 0; p < 2; p++) {
                int kr = ks * 16 + (lane & 7) + ((lane >> 4) << 3);
                int nc = wn * 32 + p * 16 + (((lane >> 3) & 1) << 3);
                uint32_t r0, r1, r2, r3;
                ldmx4t(r0, r1, r2, r3, vB + (uint32_t)(V_SZ + kr * VSTR + nc) * 2);
                bv[2 * p][0] = r0; bv[2 * p][1] = r2; bv[2 * p + 1][0] = r1; bv[2 * p + 1][1] = r3;
            }
            #pragma unroll
            for (int mt = 0; mt < 2; mt++)
                #pragma unroll
                for (int nt = 0; nt < 4; nt++)
                    mma16816(acc[mt][nt], wh[mt][0], wh[mt][1], wh[mt][2], wh[mt][3], bv[nt][0], bv[nt][1]);
        }
    };

    constexpr int NKI = SEQ / 32;
    // prologue: P stage 0 staged in smem pre-loop (consumed after iter-0
    // barrier), V stage 0 in flight.
    loadE(0);
    storeA(0, 0);
    cpaV(0, 0);
    for (int t = 0; t < NKI; t++) {
        if (t + 1 < NKI) { loadE((t + 1) * 32); cpaV((t + 1) * 32, (t + 1) % 3); CP_WAIT1(); }
        else             { CP_WAIT0(); }
        __syncthreads();                  // V(t) visible; all threads done compute(t-1)
        compute(t);                       // covers the E-load + STG latency below
        if (t + 1 < NKI) storeA((t + 1) * 32, (t + 1) & 1);
        // storeA(t+1) writes P buf (t+1)&1, last read by compute(t-1) — every
        // thread passed that before this iteration's barrier. compute(t+1)'s
        // reads are ordered by the next iteration's barrier.
    }

    // epilogue: split context to bf16 hi/lo
    bf16* Chz = Coh + zo * BG_STRIDE + (long long)zi * HDIM;
    bf16* Clz = Col + zo * BG_STRIDE + (long long)zi * HDIM;
    #pragma unroll
    for (int mt = 0; mt < 2; mt++) {
        int r = row0 + wm * 32 + mt * 16 + (lane >> 2);
        #pragma unroll
        for (int nt = 0; nt < 4; nt++) {
            int c = wn * 32 + nt * 8 + ((lane & 3) << 1);
            ushortT h0, l0, h1, l1, h2, l2, h3, l3;
            bsplit(acc[mt][nt][0], h0, l0); bsplit(acc[mt][nt][1], h1, l1);
            bsplit(acc[mt][nt][2], h2, l2); bsplit(acc[mt][nt][3], h3, l3);
            *reinterpret_cast<uint32_t*>(Chz + (long long)r * CH + c)       = pack2(h0, h1);
            *reinterpret_cast<uint32_t*>(Clz + (long long)r * CH + c)       = pack2(l0, l1);
            *reinterpret_cast<uint32_t*>(Chz + (long long)(r + 8) * CH + c) = pack2(h2, h3);
            *reinterpret_cast<uint32_t*>(Clz + (long long)(r + 8) * CH + c) = pack2(l2, l3);
        }
    }
}

// ---------------------------------------------------------------------------
// Launch
// ---------------------------------------------------------------------------
extern "C" void kernel_launch(void* const* d_in, const int* in_sizes, int n_in,
                              void* d_out, int out_size)
{
    const float* xq  = (const float*)d_in[0];
    const float* xkv = (const float*)d_in[1];
    const float* Wq  = (const float*)d_in[2];
    const float* bq  = (const float*)d_in[3];
    const float* Wk  = (const float*)d_in[4];
    const float* bk  = (const float*)d_in[5];
    const float* Wv  = (const float*)d_in[6];
    const float* bv  = (const float*)d_in[7];
    const float* Wo  = (const float*)d_in[8];
    const float* bo  = (const float*)d_in[9];

    float* out   = (float*)d_out;
    float* probs = out + (long long)ROWS * CH;

    bf16 *Xqh, *Xql, *Xkh, *Xkl, *Wqh, *Wql, *Wkh, *Wkl, *Wvh, *Wvl, *Woh, *Wol;
    bf16 *Qh, *Ql, *Kh, *Kl, *Vh, *Vl, *Ch, *Cl;
    float* rsum;
    cudaGetSymbolAddress((void**)&Xqh, g_Xqh); cudaGetSymbolAddress((void**)&Xql, g_Xql);
    cudaGetSymbolAddress((void**)&Xkh, g_Xkh); cudaGetSymbolAddress((void**)&Xkl, g_Xkl);
    cudaGetSymbolAddress((void**)&Wqh, g_Wqh); cudaGetSymbolAddress((void**)&Wql, g_Wql);
    cudaGetSymbolAddress((void**)&Wkh, g_Wkh); cudaGetSymbolAddress((void**)&Wkl, g_Wkl);
    cudaGetSymbolAddress((void**)&Wvh, g_Wvh); cudaGetSymbolAddress((void**)&Wvl, g_Wvl);
    cudaGetSymbolAddress((void**)&Woh, g_Woh); cudaGetSymbolAddress((void**)&Wol, g_Wol);
    cudaGetSymbolAddress((void**)&Qh, g_Qh);   cudaGetSymbolAddress((void**)&Ql, g_Ql);
    cudaGetSymbolAddress((void**)&Kh, g_Kh);   cudaGetSymbolAddress((void**)&Kl, g_Kl);
    cudaGetSymbolAddress((void**)&Vh, g_Vh);   cudaGetSymbolAddress((void**)&Vl, g_Vl);
    cudaGetSymbolAddress((void**)&Ch, g_Ch);   cudaGetSymbolAddress((void**)&Cl, g_Cl);
    cudaGetSymbolAddress((void**)&rsum, g_rowsum);

    cudaFuncSetAttribute((const void*)proj_kernel,  cudaFuncAttributeMaxDynamicSharedMemorySize, SM_DENSE);
    cudaFuncSetAttribute((const void*)out_kernel,   cudaFuncAttributeMaxDynamicSharedMemorySize, SM_DENSE);
    cudaFuncSetAttribute((const void*)score_kernel, cudaFuncAttributeMaxDynamicSharedMemorySize, SM_SCORE);
    cudaFuncSetAttribute((const void*)pv_kernel,    cudaFuncAttributeMaxDynamicSharedMemorySize, SM_PV);

    // 0. fused splits (xq, xkv, Wq, Wk, Wv, Wo) + rowsum zeroing, one launch
    SplitAll sa;
    sa.src[0] = xq;  sa.h[0] = Xqh; sa.l[0] = Xql;
    sa.src[1] = xkv; sa.h[1] = Xkh; sa.l[1] = Xkl;
    sa.src[2] = Wq;  sa.h[2] = Wqh; sa.l[2] = Wql;
    sa.src[3] = Wk;  sa.h[3] = Wkh; sa.l[3] = Wkl;
    sa.src[4] = Wv;  sa.h[4] = Wvh; sa.l[4] = Wvl;
    sa.src[5] = Wo;  sa.h[5] = Woh; sa.l[5] = Wol;
    sa.rsum = rsum;
    split_all<<<2 * 4096 + 4 * 1024, 256>>>(sa);

    // 1. fused Q/K/V projections (grid.z = 3)
    ProjArgs pa;
    pa.Ah[0] = Xqh; pa.Al[0] = Xql; pa.Bh[0] = Wqh; pa.Bl[0] = Wql; pa.Ch[0] = Qh; pa.Cl[0] = Ql; pa.bias[0] = bq;
    pa.Ah[1] = Xkh; pa.Al[1] = Xkl; pa.Bh[1] = Wkh; pa.Bl[1] = Wkl; pa.Ch[1] = Kh; pa.Cl[1] = Kl; pa.bias[1] = bk;
    pa.Ah[2] = Xkh; pa.Al[2] = Xkl; pa.Bh[2] = Wvh; pa.Bl[2] = Wvl; pa.Ch[2] = Vh; pa.Cl[2] = Vl; pa.bias[2] = bv;
    proj_kernel<<<dim3(CH / 128, ROWS / 128, 3), 256, SM_DENSE>>>(pa);

    // 2. scores: E = exp(s/8) + row sums (single-phase, K resident)
    score_kernel<<<dim3(SEQ / 128, SEQ / 128, BG * HEADS), 256, SM_SCORE>>>(Qh, Ql, Kh, Kl, probs, rsum);

    // 3. PV: normalize probs in place + context (bf16 hi/lo)
    pv_kernel<<<dim3(1, SEQ / 128, BG * HEADS), 256, SM_PV>>>(probs, Vh, Vl, rsum, Ch, Cl);

    // 4. output projection (fp32 out)
    out_kernel<<<dim3(CH / 128, ROWS / 128, 1), 256, SM_DENSE>>>(Ch, Cl, Woh, Wol, out, bo);
}